// round 1
// baseline (speedup 1.0000x reference)
#include <cuda_runtime.h>
#include <math.h>

#define Nn   50000
#define Ee   500000
#define FIN  64
#define EIN  16
#define Hh   100
#define LL   2
#define BN_EPS 1e-5f

// ---------------- scratch (static device globals; no allocation) -------------
__device__ float g_h   [Nn * Hh];            // 20 MB
__device__ float g_e   [(size_t)Ee * Hh];    // 200 MB
__device__ float g_agg [Nn * Hh];
__device__ float g_zin [Nn * Hh];
__device__ float g_t   [Nn * Hh];
__device__ float g_z   [Nn * Hh];
__device__ float g_cat [(size_t)Ee * 3 * Hh]; // 600 MB
__device__ float g_t1  [(size_t)Ee * Hh];     // 200 MB
__device__ float g_o1  [(size_t)Ee * 50];
__device__ float g_o2  [(size_t)Ee * 25];
__device__ float g_stats[2 * Hh];

// ---------------- utility kernels -------------------------------------------
__global__ void zero_k(float* __restrict__ p, int n) {
    int i = blockIdx.x * blockDim.x + threadIdx.x;
    if (i < n) p[i] = 0.f;
}

__global__ void add_k(const float* __restrict__ a, const float* __restrict__ b,
                      float* __restrict__ c, int n) {
    int i = blockIdx.x * blockDim.x + threadIdx.x;
    if (i < n) c[i] = a[i] + b[i];
}

// msg = relu(h[src] + e), scatter-add into agg[dst]. One block per edge.
__global__ void scatter_k(const float* __restrict__ h, const float* __restrict__ e,
                          const int* __restrict__ src, const int* __restrict__ dst,
                          float* __restrict__ agg) {
    int ed = blockIdx.x;
    int s = src[ed], d = dst[ed];
    const float* hr = h + (size_t)s * Hh;
    const float* er = e + (size_t)ed * Hh;
    float* ar = agg + (size_t)d * Hh;
    for (int j = threadIdx.x; j < Hh; j += blockDim.x) {
        float m = hr[j] + er[j];
        if (m > 0.f) atomicAdd(&ar[j], m);   // relu: skip non-positive adds
    }
}

// per-column sum / sumsq over nodes. blockDim=128 (100 active lanes).
__global__ void bn_stats_k(const float* __restrict__ z, float* __restrict__ stats) {
    int j = threadIdx.x;
    if (j >= Hh) return;
    int r0 = blockIdx.x * 256;
    int r1 = min(r0 + 256, Nn);
    float s = 0.f, ss = 0.f;
    for (int r = r0; r < r1; r++) {
        float v = z[(size_t)r * Hh + j];
        s += v;
        ss = fmaf(v, v, ss);
    }
    atomicAdd(&stats[j], s);
    atomicAdd(&stats[Hh + j], ss);
}

// h = (h + relu(batchnorm(z))) * 0.5
__global__ void hupd_k(float* __restrict__ h, const float* __restrict__ z,
                       const float* __restrict__ stats,
                       const float* __restrict__ gamma, const float* __restrict__ beta) {
    int idx = blockIdx.x * blockDim.x + threadIdx.x;
    if (idx >= Nn * Hh) return;
    int j = idx % Hh;
    float mu  = stats[j] * (1.0f / Nn);
    float var = fmaf(-mu, mu, stats[Hh + j] * (1.0f / Nn));
    float zn  = (z[idx] - mu) * rsqrtf(var + BN_EPS) * gamma[j] + beta[j];
    h[idx] = (h[idx] + fmaxf(zn, 0.f)) * 0.5f;
}

// cat = [ (relu?)h[src], (relu?)h[dst], e ]   -> [E, 300]
template<bool RELU_NODES>
__global__ void cat_k(const float* __restrict__ h, const float* __restrict__ e,
                      const int* __restrict__ src, const int* __restrict__ dst,
                      float* __restrict__ cat) {
    int ed = blockIdx.x;
    int s = src[ed], d = dst[ed];
    const float* hs = h + (size_t)s * Hh;
    const float* hd = h + (size_t)d * Hh;
    const float* er = e + (size_t)ed * Hh;
    float* c = cat + (size_t)ed * 3 * Hh;
    for (int j = threadIdx.x; j < Hh; j += blockDim.x) {
        float a = hs[j], b = hd[j];
        if (RELU_NODES) { a = fmaxf(a, 0.f); b = fmaxf(b, 0.f); }
        c[j]          = a;
        c[Hh + j]     = b;
        c[2 * Hh + j] = er[j];
    }
}

// ---------------- generic tiled GEMM  C[M,Jn] = A[M,K] @ W[K,Jn] + bias ------
// EPI: 0 = store, 1 = relu-store, 2 = C += 0.5 * (acc + bias)
// block (32,8); tile: 64 rows x up to 128 cols; TK = 32
template<int EPI>
__global__ void __launch_bounds__(256)
gemm_k(const float* __restrict__ A, const float* __restrict__ W,
       const float* __restrict__ bias, float* __restrict__ C,
       int M, int K, int Jn) {
    __shared__ float As[64][32];
    __shared__ float Ws[32][128];
    const int tx = threadIdx.x, ty = threadIdx.y;
    const int tid = ty * 32 + tx;
    const int row0 = blockIdx.y * 64;
    const int j0 = blockIdx.x * 128;
    const int jc = min(128, Jn - j0);
    float acc[8][4] = {};

    for (int k0 = 0; k0 < K; k0 += 32) {
        #pragma unroll
        for (int i = 0; i < 8; i++) {
            int idx = tid + i * 256;
            int m = idx >> 5, k = idx & 31;
            int gr = row0 + m, gk = k0 + k;
            As[m][k] = (gr < M && gk < K) ? A[(size_t)gr * K + gk] : 0.f;
        }
        for (int idx = tid; idx < 32 * jc; idx += 256) {
            int k = idx / jc, j = idx - k * jc;
            int gk = k0 + k;
            Ws[k][j] = (gk < K) ? W[(size_t)gk * Jn + j0 + j] : 0.f;
        }
        __syncthreads();
        #pragma unroll
        for (int k = 0; k < 32; k++) {
            float b0 = Ws[k][tx], b1 = Ws[k][tx + 32];
            float b2 = Ws[k][tx + 64], b3 = Ws[k][tx + 96];
            #pragma unroll
            for (int r = 0; r < 8; r++) {
                float a = As[ty + 8 * r][k];
                acc[r][0] = fmaf(a, b0, acc[r][0]);
                acc[r][1] = fmaf(a, b1, acc[r][1]);
                acc[r][2] = fmaf(a, b2, acc[r][2]);
                acc[r][3] = fmaf(a, b3, acc[r][3]);
            }
        }
        __syncthreads();
    }
    #pragma unroll
    for (int r = 0; r < 8; r++) {
        int row = row0 + ty + 8 * r;
        if (row >= M) continue;
        #pragma unroll
        for (int q = 0; q < 4; q++) {
            int j = j0 + tx + 32 * q;
            if (j >= Jn) continue;
            float v = acc[r][q] + bias[j];
            if (EPI == 1) v = fmaxf(v, 0.f);
            if (EPI == 2) C[(size_t)row * Jn + j] += 0.5f * v;
            else          C[(size_t)row * Jn + j] = v;
        }
    }
}

// out[E,2] = o2[E,25] @ w3[25,2] + b3
__global__ void final_k(const float* __restrict__ o2, const float* __restrict__ w3,
                        const float* __restrict__ b3, float* __restrict__ out) {
    int r = blockIdx.x * blockDim.x + threadIdx.x;
    if (r >= Ee) return;
    float a0 = b3[0], a1 = b3[1];
    const float* row = o2 + (size_t)r * 25;
    #pragma unroll
    for (int k = 0; k < 25; k++) {
        float v = row[k];
        a0 = fmaf(v, w3[k * 2 + 0], a0);
        a1 = fmaf(v, w3[k * 2 + 1], a1);
    }
    out[(size_t)r * 2 + 0] = a0;
    out[(size_t)r * 2 + 1] = a1;
}

// ---------------- launcher ---------------------------------------------------
static inline int cdiv(int a, int b) { return (a + b - 1) / b; }

extern "C" void kernel_launch(void* const* d_in, const int* in_sizes, int n_in,
                              void* d_out, int out_size) {
    const float* x        = (const float*)d_in[0];
    const float* edge_attr= (const float*)d_in[1];
    const int*   ei       = (const int*)  d_in[2];
    const float* node_w   = (const float*)d_in[3];
    const float* node_b   = (const float*)d_in[4];
    const float* edge_w   = (const float*)d_in[5];
    const float* edge_b   = (const float*)d_in[6];
    const float* gw1      = (const float*)d_in[7];
    const float* gb1      = (const float*)d_in[8];
    const float* gw2      = (const float*)d_in[9];
    const float* gb2      = (const float*)d_in[10];
    const float* bng      = (const float*)d_in[11];
    const float* bnb      = (const float*)d_in[12];
    const float* ew1      = (const float*)d_in[13];
    const float* eb1      = (const float*)d_in[14];
    const float* ew2      = (const float*)d_in[15];
    const float* eb2      = (const float*)d_in[16];
    const float* mw1      = (const float*)d_in[17];
    const float* mb1      = (const float*)d_in[18];
    const float* mw2      = (const float*)d_in[19];
    const float* mb2      = (const float*)d_in[20];
    const float* mw3      = (const float*)d_in[21];
    const float* mb3      = (const float*)d_in[22];
    float* out = (float*)d_out;

    void* p;
    cudaGetSymbolAddress(&p, g_h);    float* h    = (float*)p;
    cudaGetSymbolAddress(&p, g_e);    float* e    = (float*)p;
    cudaGetSymbolAddress(&p, g_agg);  float* agg  = (float*)p;
    cudaGetSymbolAddress(&p, g_zin);  float* zin  = (float*)p;
    cudaGetSymbolAddress(&p, g_t);    float* t    = (float*)p;
    cudaGetSymbolAddress(&p, g_z);    float* z    = (float*)p;
    cudaGetSymbolAddress(&p, g_cat);  float* cat  = (float*)p;
    cudaGetSymbolAddress(&p, g_t1);   float* t1   = (float*)p;
    cudaGetSymbolAddress(&p, g_o1);   float* o1   = (float*)p;
    cudaGetSymbolAddress(&p, g_o2);   float* o2   = (float*)p;
    cudaGetSymbolAddress(&p, g_stats);float* st   = (float*)p;

    const int* src = ei;
    const int* dst = ei + Ee;
    dim3 gb(32, 8);

    // embeddings
    gemm_k<0><<<dim3(1, cdiv(Nn, 64)), gb>>>(x,         node_w, node_b, h, Nn, FIN, Hh);
    gemm_k<0><<<dim3(1, cdiv(Ee, 64)), gb>>>(edge_attr, edge_w, edge_b, e, Ee, EIN, Hh);

    for (int l = 0; l < LL; l++) {
        zero_k<<<cdiv(Nn * Hh, 256), 256>>>(agg, Nn * Hh);
        scatter_k<<<Ee, 128>>>(h, e, src, dst, agg);
        add_k<<<cdiv(Nn * Hh, 256), 256>>>(h, agg, zin, Nn * Hh);
        gemm_k<1><<<dim3(1, cdiv(Nn, 64)), gb>>>(zin, gw1 + (size_t)l * Hh * Hh, gb1 + l * Hh, t, Nn, Hh, Hh);
        gemm_k<0><<<dim3(1, cdiv(Nn, 64)), gb>>>(t,   gw2 + (size_t)l * Hh * Hh, gb2 + l * Hh, z, Nn, Hh, Hh);
        zero_k<<<1, 256>>>(st, 2 * Hh);
        bn_stats_k<<<cdiv(Nn, 256), 128>>>(z, st);
        hupd_k<<<cdiv(Nn * Hh, 256), 256>>>(h, z, st, bng + l * Hh, bnb + l * Hh);
        cat_k<false><<<Ee, 128>>>(h, e, src, dst, cat);
        gemm_k<1><<<dim3(1, cdiv(Ee, 64)), gb>>>(cat, ew1 + (size_t)l * 3 * Hh * Hh, eb1 + l * Hh, t1, Ee, 3 * Hh, Hh);
        gemm_k<2><<<dim3(1, cdiv(Ee, 64)), gb>>>(t1,  ew2 + (size_t)l * Hh * Hh,     eb2 + l * Hh, e,  Ee, Hh, Hh);
    }

    // readout
    cat_k<true><<<Ee, 128>>>(h, e, src, dst, cat);
    gemm_k<1><<<dim3(1, cdiv(Ee, 64)), gb>>>(cat, mw1, mb1, o1, Ee, 3 * Hh, 50);
    gemm_k<1><<<dim3(1, cdiv(Ee, 64)), gb>>>(o1,  mw2, mb2, o2, Ee, 50, 25);
    final_k<<<cdiv(Ee, 256), 256>>>(o2, mw3, mb3, out);
}

// round 4
// speedup vs baseline: 1.4157x; 1.4157x over previous
#include <cuda_runtime.h>
#include <math.h>
#include <string.h>

#define Nn   50000
#define Ee   500000
#define FIN  64
#define EIN  16
#define Hh   100
#define LL   2
#define BN_EPS 1e-5f

// ---------------- scratch (static device globals; no allocation) -------------
__device__ float g_h   [Nn * Hh];
__device__ float g_e   [(size_t)Ee * Hh];    // 200 MB
__device__ float g_agg [Nn * Hh];
__device__ float g_t   [Nn * Hh];
__device__ float g_z   [Nn * Hh];
__device__ float g_Ha  [Nn * Hh];
__device__ float g_Hb  [Nn * Hh];
__device__ float g_HRa [Nn * 50];
__device__ float g_HRb [Nn * 50];
__device__ float g_t1  [(size_t)Ee * Hh];    // 200 MB
__device__ float g_o1  [(size_t)Ee * 50];    // 100 MB
__device__ float g_stats[2 * Hh];
__device__ float g_zb  [Hh];                 // zero bias

// ---------------- utility kernels -------------------------------------------
__global__ void zero_k(float* __restrict__ p, int n) {
    int i = blockIdx.x * blockDim.x + threadIdx.x;
    if (i < n) p[i] = 0.f;
}

// msg = relu(h[src] + e), scatter-add into agg[dst]. One block per edge.
__global__ void scatter_k(const float* __restrict__ h, const float* __restrict__ e,
                          const int* __restrict__ src, const int* __restrict__ dst,
                          float* __restrict__ agg) {
    int ed = blockIdx.x;
    int s = src[ed], d = dst[ed];
    const float* hr = h + (size_t)s * Hh;
    const float* er = e + (size_t)ed * Hh;
    float* ar = agg + (size_t)d * Hh;
    for (int j = threadIdx.x; j < Hh; j += blockDim.x) {
        float m = hr[j] + er[j];
        if (m > 0.f) atomicAdd(&ar[j], m);
    }
}

// per-column sum / sumsq over nodes
__global__ void bn_stats_k(const float* __restrict__ z, float* __restrict__ stats) {
    int j = threadIdx.x;
    if (j >= Hh) return;
    int r0 = blockIdx.x * 256;
    int r1 = min(r0 + 256, Nn);
    float s = 0.f, ss = 0.f;
    for (int r = r0; r < r1; r++) {
        float v = z[(size_t)r * Hh + j];
        s += v;
        ss = fmaf(v, v, ss);
    }
    atomicAdd(&stats[j], s);
    atomicAdd(&stats[Hh + j], ss);
}

// h = (h + relu(batchnorm(z))) * 0.5
__global__ void hupd_k(float* __restrict__ h, const float* __restrict__ z,
                       const float* __restrict__ stats,
                       const float* __restrict__ gamma, const float* __restrict__ beta) {
    int idx = blockIdx.x * blockDim.x + threadIdx.x;
    if (idx >= Nn * Hh) return;
    int j = idx % Hh;
    float mu  = stats[j] * (1.0f / Nn);
    float var = fmaf(-mu, mu, stats[Hh + j] * (1.0f / Nn));
    float zn  = (z[idx] - mu) * rsqrtf(var + BN_EPS) * gamma[j] + beta[j];
    h[idx] = (h[idx] + fmaxf(zn, 0.f)) * 0.5f;
}

// ---------------- packed-fp32 GEMM ------------------------------------------
// C[M, 2*JP] = op(A)[M, KT] @ W[KT, 2*JP]  (+ epilogue)
// Tile: 40 rows x 2*JP cols, block (25,10) = 250 threads, thread = 4 rows x P pairs.
// A stored in smem duplicated ({a,a}) so FFMA2 operands come from LDS.64 directly.
// PRO: 0 plain, 1 A+A2, 2 relu(A)
// EPI: 0 store+bias, 1 relu store, 2 C += 0.5*(acc+bias),
//      3 relu(acc + bias + Ta[src[row]] + Tb[dst[row]]) store
template<int KT, int JP, int PRO, int EPI>
__global__ void __launch_bounds__(256, 3)
gemm2_k(const float* __restrict__ A, const float* __restrict__ A2,
        const float* __restrict__ W, const float* __restrict__ bias,
        float* __restrict__ C,
        const int* __restrict__ src, const int* __restrict__ dst,
        const float* __restrict__ Ta, const float* __restrict__ Tb) {
    constexpr int JN = 2 * JP;
    constexpr int P  = JP / 25;
    extern __shared__ float sm[];
    float*  Ws  = sm;                                  // KT*JN floats
    float2* As2 = (float2*)(sm + KT * JN);             // 40*(KT+1) float2
    const int x = threadIdx.x, y = threadIdx.y;
    const int tid = y * 25 + x;
    const int row0 = blockIdx.x * 40;

    for (int idx = tid; idx < KT * JN; idx += 250) Ws[idx] = W[idx];
    for (int idx = tid; idx < 40 * KT; idx += 250) {
        int i = idx / KT, k = idx - i * KT;
        size_t g = (size_t)(row0 + i) * KT + k;
        float v = A[g];
        if (PRO == 1) v += A2[g];
        if (PRO == 2) v = fmaxf(v, 0.f);
        As2[i * (KT + 1) + k] = make_float2(v, v);
    }
    __syncthreads();

    unsigned long long acc[4][P];
    #pragma unroll
    for (int r = 0; r < 4; r++)
        #pragma unroll
        for (int p = 0; p < P; p++) acc[r][p] = 0ULL;

    const unsigned long long* WsU = (const unsigned long long*)Ws;
    const unsigned long long* AsU = (const unsigned long long*)As2;

    #pragma unroll
    for (int k = 0; k < KT; k++) {
        unsigned long long b[P];
        #pragma unroll
        for (int p = 0; p < P; p++) b[p] = WsU[k * JP + x + 25 * p];
        #pragma unroll
        for (int r = 0; r < 4; r++) {
            unsigned long long a = AsU[(y + 10 * r) * (KT + 1) + k];
            #pragma unroll
            for (int p = 0; p < P; p++)
                asm("fma.rn.f32x2 %0, %1, %2, %0;" : "+l"(acc[r][p]) : "l"(a), "l"(b[p]));
        }
    }

    #pragma unroll
    for (int r = 0; r < 4; r++) {
        int row = row0 + y + 10 * r;
        int s = 0, d = 0;
        if (EPI == 3) { s = src[row]; d = dst[row]; }
        #pragma unroll
        for (int p = 0; p < P; p++) {
            int c0 = 2 * (x + 25 * p);
            float2 f;
            memcpy(&f, &acc[r][p], 8);
            float v0 = f.x + bias[c0];
            float v1 = f.y + bias[c0 + 1];
            float2* cp = (float2*)(C + (size_t)row * JN + c0);
            if (EPI == 0) {
                *cp = make_float2(v0, v1);
            } else if (EPI == 1) {
                *cp = make_float2(fmaxf(v0, 0.f), fmaxf(v1, 0.f));
            } else if (EPI == 2) {
                float2 old = *cp;
                *cp = make_float2(fmaf(0.5f, v0, old.x), fmaf(0.5f, v1, old.y));
            } else {
                float2 ta = *(const float2*)(Ta + (size_t)s * JN + c0);
                float2 tb = *(const float2*)(Tb + (size_t)d * JN + c0);
                *cp = make_float2(fmaxf(v0 + ta.x + tb.x, 0.f),
                                  fmaxf(v1 + ta.y + tb.y, 0.f));
            }
        }
    }
}

// fused tail: out = relu(o1@w2+b2) @ w3 + b3  per edge
__global__ void __launch_bounds__(256)
final_fused_k(const float* __restrict__ o1,
              const float* __restrict__ w2, const float* __restrict__ b2,
              const float* __restrict__ w3, const float* __restrict__ b3,
              float* __restrict__ out) {
    __shared__ float sw2[50 * 25];
    __shared__ float sw3[50];
    __shared__ float sb2[25];
    __shared__ float sb3[2];
    int t = threadIdx.x;
    for (int i = t; i < 1250; i += 256) sw2[i] = w2[i];
    if (t < 50) sw3[t] = w3[t];
    if (t < 25) sb2[t] = b2[t];
    if (t < 2)  sb3[t] = b3[t];
    __syncthreads();
    int r = blockIdx.x * 256 + t;
    if (r >= Ee) return;
    float a[50];
    const float2* row = (const float2*)(o1 + (size_t)r * 50);
    #pragma unroll
    for (int i = 0; i < 25; i++) { float2 v = row[i]; a[2*i] = v.x; a[2*i+1] = v.y; }
    float out0 = sb3[0], out1 = sb3[1];
    #pragma unroll 5
    for (int j = 0; j < 25; j++) {
        float s = sb2[j];
        #pragma unroll
        for (int k = 0; k < 50; k++) s = fmaf(a[k], sw2[k * 25 + j], s);
        s = fmaxf(s, 0.f);
        out0 = fmaf(s, sw3[2 * j],     out0);
        out1 = fmaf(s, sw3[2 * j + 1], out1);
    }
    out[(size_t)r * 2]     = out0;
    out[(size_t)r * 2 + 1] = out1;
}

// ---------------- launcher ---------------------------------------------------
static inline int cdiv(int a, int b) { return (a + b - 1) / b; }

template<int KT, int JP, int PRO, int EPI>
static void launch_gemm(int M, const float* A, const float* A2,
                        const float* W, const float* bias, float* C,
                        const int* src = nullptr, const int* dst = nullptr,
                        const float* Ta = nullptr, const float* Tb = nullptr) {
    int smem = KT * 2 * JP * 4 + 40 * (KT + 1) * 8;
    cudaFuncSetAttribute(gemm2_k<KT, JP, PRO, EPI>,
                         cudaFuncAttributeMaxDynamicSharedMemorySize, smem);
    gemm2_k<KT, JP, PRO, EPI><<<M / 40, dim3(25, 10), smem>>>(
        A, A2, W, bias, C, src, dst, Ta, Tb);
}

extern "C" void kernel_launch(void* const* d_in, const int* in_sizes, int n_in,
                              void* d_out, int out_size) {
    const float* x        = (const float*)d_in[0];
    const float* edge_attr= (const float*)d_in[1];
    const int*   ei       = (const int*)  d_in[2];
    const float* node_w   = (const float*)d_in[3];
    const float* node_b   = (const float*)d_in[4];
    const float* edge_w   = (const float*)d_in[5];
    const float* edge_b   = (const float*)d_in[6];
    const float* gw1      = (const float*)d_in[7];
    const float* gb1      = (const float*)d_in[8];
    const float* gw2      = (const float*)d_in[9];
    const float* gb2      = (const float*)d_in[10];
    const float* bng      = (const float*)d_in[11];
    const float* bnb      = (const float*)d_in[12];
    const float* ew1      = (const float*)d_in[13];
    const float* eb1      = (const float*)d_in[14];
    const float* ew2      = (const float*)d_in[15];
    const float* eb2      = (const float*)d_in[16];
    const float* mw1      = (const float*)d_in[17];
    const float* mb1      = (const float*)d_in[18];
    const float* mw2      = (const float*)d_in[19];
    const float* mb2      = (const float*)d_in[20];
    const float* mw3      = (const float*)d_in[21];
    const float* mb3      = (const float*)d_in[22];
    float* out = (float*)d_out;

    void* p;
    cudaGetSymbolAddress(&p, g_h);    float* h    = (float*)p;
    cudaGetSymbolAddress(&p, g_e);    float* e    = (float*)p;
    cudaGetSymbolAddress(&p, g_agg);  float* agg  = (float*)p;
    cudaGetSymbolAddress(&p, g_t);    float* t    = (float*)p;
    cudaGetSymbolAddress(&p, g_z);    float* z    = (float*)p;
    cudaGetSymbolAddress(&p, g_Ha);   float* Ha   = (float*)p;
    cudaGetSymbolAddress(&p, g_Hb);   float* Hb   = (float*)p;
    cudaGetSymbolAddress(&p, g_HRa);  float* HRa  = (float*)p;
    cudaGetSymbolAddress(&p, g_HRb);  float* HRb  = (float*)p;
    cudaGetSymbolAddress(&p, g_t1);   float* t1   = (float*)p;
    cudaGetSymbolAddress(&p, g_o1);   float* o1   = (float*)p;
    cudaGetSymbolAddress(&p, g_stats);float* st   = (float*)p;
    cudaGetSymbolAddress(&p, g_zb);   float* zb   = (float*)p;

    const int* src = ei;
    const int* dst = ei + Ee;

    zero_k<<<1, 128>>>(zb, Hh);

    // embeddings
    launch_gemm<FIN, 50, 0, 0>(Nn, x,         nullptr, node_w, node_b, h);
    launch_gemm<EIN, 50, 0, 0>(Ee, edge_attr, nullptr, edge_w, edge_b, e);

    for (int l = 0; l < LL; l++) {
        // message passing
        zero_k<<<cdiv(Nn * Hh, 256), 256>>>(agg, Nn * Hh);
        scatter_k<<<Ee, 128>>>(h, e, src, dst, agg);
        // GINE MLP: t = relu((h+agg)@gw1+b1); z = t@gw2+b2
        launch_gemm<100, 50, 1, 1>(Nn, h, agg, gw1 + (size_t)l * 10000, gb1 + l * Hh, t);
        launch_gemm<100, 50, 0, 0>(Nn, t, nullptr, gw2 + (size_t)l * 10000, gb2 + l * Hh, z);
        // BN + residual
        zero_k<<<1, 256>>>(st, 2 * Hh);
        bn_stats_k<<<cdiv(Nn, 256), 128>>>(z, st);
        hupd_k<<<cdiv(Nn * Hh, 256), 256>>>(h, z, st, bng + l * Hh, bnb + l * Hh);
        // edge update, decomposed: Ha=h@W_a, Hb=h@W_b (node level)
        launch_gemm<100, 50, 0, 0>(Nn, h, nullptr, ew1 + (size_t)l * 30000,         zb, Ha);
        launch_gemm<100, 50, 0, 0>(Nn, h, nullptr, ew1 + (size_t)l * 30000 + 10000, zb, Hb);
        // t1 = relu(e@W_c + Ha[src] + Hb[dst] + b1)
        launch_gemm<100, 50, 0, 3>(Ee, e, nullptr, ew1 + (size_t)l * 30000 + 20000,
                                   eb1 + l * Hh, t1, src, dst, Ha, Hb);
        // e += 0.5*(t1@ew2 + b2)
        launch_gemm<100, 50, 0, 2>(Ee, t1, nullptr, ew2 + (size_t)l * 10000, eb2 + l * Hh, e);
    }

    // readout: HRa = relu(h)@mw1_a, HRb = relu(h)@mw1_b (node level)
    launch_gemm<100, 25, 2, 0>(Nn, h, nullptr, mw1,        zb, HRa);
    launch_gemm<100, 25, 2, 0>(Nn, h, nullptr, mw1 + 5000, zb, HRb);
    // o1 = relu(e@mw1_c + HRa[src] + HRb[dst] + mb1)
    launch_gemm<100, 25, 0, 3>(Ee, e, nullptr, mw1 + 10000, mb1, o1, src, dst, HRa, HRb);
    // fused o2 + final
    final_fused_k<<<cdiv(Ee, 256), 256>>>(o1, mw2, mb2, mw3, mb3, out);
}

// round 5
// speedup vs baseline: 2.2748x; 1.6069x over previous
#include <cuda_runtime.h>
#include <math.h>
#include <string.h>

#define Nn   50000
#define Ee   500000
#define FIN  64
#define EIN  16
#define Hh   100
#define LL   2
#define BN_EPS 1e-5f

// ---------------- scratch (static device globals; no allocation) -------------
__device__ float g_h   [Nn * Hh];
__device__ float g_e   [(size_t)Ee * Hh];
__device__ float g_agg [Nn * Hh];
__device__ float g_t   [Nn * Hh];
__device__ float g_z   [Nn * Hh];
__device__ float g_Ha  [Nn * Hh];
__device__ float g_Hb  [Nn * Hh];
__device__ float g_HRa [Nn * 50];
__device__ float g_HRb [Nn * 50];
__device__ float g_t1  [(size_t)Ee * Hh];
__device__ float g_o1  [(size_t)Ee * 50];
__device__ float g_stats[2 * Hh];
__device__ float g_zb  [Hh];

// ---------------- utility kernels -------------------------------------------
__global__ void zero_k(float* __restrict__ p, int n) {
    int i = blockIdx.x * blockDim.x + threadIdx.x;
    if (i < n) p[i] = 0.f;
}

// msg = relu(h[src] + e), scatter-add into agg[dst]
__global__ void scatter_k(const float* __restrict__ h, const float* __restrict__ e,
                          const int* __restrict__ src, const int* __restrict__ dst,
                          float* __restrict__ agg) {
    int ed = blockIdx.x;
    int s = src[ed], d = dst[ed];
    const float* hr = h + (size_t)s * Hh;
    const float* er = e + (size_t)ed * Hh;
    float* ar = agg + (size_t)d * Hh;
    for (int j = threadIdx.x; j < Hh; j += blockDim.x) {
        float m = hr[j] + er[j];
        if (m > 0.f) atomicAdd(&ar[j], m);
    }
}

__global__ void bn_stats_k(const float* __restrict__ z, float* __restrict__ stats) {
    int j = threadIdx.x;
    if (j >= Hh) return;
    int r0 = blockIdx.x * 256;
    int r1 = min(r0 + 256, Nn);
    float s = 0.f, ss = 0.f;
    for (int r = r0; r < r1; r++) {
        float v = z[(size_t)r * Hh + j];
        s += v;
        ss = fmaf(v, v, ss);
    }
    atomicAdd(&stats[j], s);
    atomicAdd(&stats[Hh + j], ss);
}

__global__ void hupd_k(float* __restrict__ h, const float* __restrict__ z,
                       const float* __restrict__ stats,
                       const float* __restrict__ gamma, const float* __restrict__ beta) {
    int idx = blockIdx.x * blockDim.x + threadIdx.x;
    if (idx >= Nn * Hh) return;
    int j = idx % Hh;
    float mu  = stats[j] * (1.0f / Nn);
    float var = fmaf(-mu, mu, stats[Hh + j] * (1.0f / Nn));
    float zn  = (z[idx] - mu) * rsqrtf(var + BN_EPS) * gamma[j] + beta[j];
    h[idx] = (h[idx] + fmaxf(zn, 0.f)) * 0.5f;
}

// ---------------- K-paired packed-fp32 GEMM ----------------------------------
// C[M, 25*JT] = op(A)[M,KT] @ W[KT, 25*JT] + epilogue.
// Tile 80 rows x 25*JT cols. Block (25,10). Thread: 8 rows x JT cols.
// Accumulators are K-split float2 (even-k in .x, odd-k in .y), combined at end.
// W transposed in smem (Wt[j][k], row stride KP floats, conflict-free),
// A row-major in smem (stride KP). All inner-loop loads are LDS.128.
// PRO: 0 plain, 1 A+A2, 2 relu(A)
// EPI: 0 store+bias, 1 relu store, 2 C += 0.5*(acc+bias),
//      3 relu(acc+bias+Ta[src[row]]+Tb[dst[row]]) store
template<int KT, int KP, int CH, int JT, int PRO, int EPI>
__global__ void __launch_bounds__(256, 2)
gemm4_k(const float* __restrict__ A, const float* __restrict__ A2,
        const float* __restrict__ W, const float* __restrict__ bias,
        float* __restrict__ C,
        const int* __restrict__ src, const int* __restrict__ dst,
        const float* __restrict__ Ta, const float* __restrict__ Tb) {
    constexpr int JN  = 25 * JT;
    constexpr int KP4 = KP / 4;
    extern __shared__ float sm[];
    float* Ws = sm;                // [JN][KP] transposed weights
    float* As = sm + JN * KP;      // [80][KP]
    const int x = threadIdx.x, y = threadIdx.y;
    const int tid = y * 25 + x;
    const int row0 = blockIdx.x * 80;

    // load W transposed (coalesced global read, strided smem write)
    for (int idx = tid; idx < KT * JN; idx += 250) {
        int k = idx / JN, j = idx - k * JN;
        Ws[j * KP + k] = W[idx];
    }
    // load A tile (coalesced)
    for (int idx = tid; idx < 80 * KT; idx += 250) {
        int i = idx / KT, k = idx - i * KT;
        size_t g = (size_t)(row0 + i) * KT + k;
        float v = A[g];
        if (PRO == 1) v += A2[g];
        if (PRO == 2) v = fmaxf(v, 0.f);
        As[i * KP + k] = v;
    }
    // zero K padding (only when CH*4 > KT)
    if (CH * 4 > KT) {
        for (int idx = tid; idx < JN * (CH * 4 - KT); idx += 250) {
            int j = idx / (CH * 4 - KT), k = KT + idx % (CH * 4 - KT);
            Ws[j * KP + k] = 0.f;
        }
        for (int idx = tid; idx < 80 * (CH * 4 - KT); idx += 250) {
            int i = idx / (CH * 4 - KT), k = KT + idx % (CH * 4 - KT);
            As[i * KP + k] = 0.f;
        }
    }
    __syncthreads();

    unsigned long long acc[8][JT];
    #pragma unroll
    for (int r = 0; r < 8; r++)
        #pragma unroll
        for (int q = 0; q < JT; q++) acc[r][q] = 0ULL;

    const ulonglong2* WsU = (const ulonglong2*)Ws;
    const ulonglong2* AsU = (const ulonglong2*)As;

    #pragma unroll 5
    for (int c = 0; c < CH; c++) {
        ulonglong2 b[JT];
        #pragma unroll
        for (int q = 0; q < JT; q++) b[q] = WsU[(x + 25 * q) * KP4 + c];
        #pragma unroll
        for (int r = 0; r < 8; r++) {
            ulonglong2 a = AsU[(y + 10 * r) * KP4 + c];
            #pragma unroll
            for (int q = 0; q < JT; q++) {
                asm("fma.rn.f32x2 %0, %1, %2, %0;" : "+l"(acc[r][q]) : "l"(a.x), "l"(b[q].x));
                asm("fma.rn.f32x2 %0, %1, %2, %0;" : "+l"(acc[r][q]) : "l"(a.y), "l"(b[q].y));
            }
        }
    }

    #pragma unroll
    for (int r = 0; r < 8; r++) {
        int row = row0 + y + 10 * r;
        const float* ta = nullptr; const float* tb = nullptr;
        if (EPI == 3) {
            ta = Ta + (size_t)src[row] * JN;
            tb = Tb + (size_t)dst[row] * JN;
        }
        #pragma unroll
        for (int q = 0; q < JT; q++) {
            int j = x + 25 * q;
            float2 f;
            memcpy(&f, &acc[r][q], 8);
            float v = f.x + f.y + bias[j];
            float* cp = C + (size_t)row * JN + j;
            if (EPI == 0)      *cp = v;
            else if (EPI == 1) *cp = fmaxf(v, 0.f);
            else if (EPI == 2) *cp = fmaf(0.5f, v, *cp);
            else               *cp = fmaxf(v + ta[j] + tb[j], 0.f);
        }
    }
}

// fused tail: out = relu(o1@w2+b2) @ w3 + b3 per edge
__global__ void __launch_bounds__(256)
final_fused_k(const float* __restrict__ o1,
              const float* __restrict__ w2, const float* __restrict__ b2,
              const float* __restrict__ w3, const float* __restrict__ b3,
              float* __restrict__ out) {
    __shared__ float sw2[50 * 25];
    __shared__ float sw3[50];
    __shared__ float sb2[25];
    __shared__ float sb3[2];
    int t = threadIdx.x;
    for (int i = t; i < 1250; i += 256) sw2[i] = w2[i];
    if (t < 50) sw3[t] = w3[t];
    if (t < 25) sb2[t] = b2[t];
    if (t < 2)  sb3[t] = b3[t];
    __syncthreads();
    int r = blockIdx.x * 256 + t;
    if (r >= Ee) return;
    float a[50];
    const float2* row = (const float2*)(o1 + (size_t)r * 50);
    #pragma unroll
    for (int i = 0; i < 25; i++) { float2 v = row[i]; a[2*i] = v.x; a[2*i+1] = v.y; }
    float out0 = sb3[0], out1 = sb3[1];
    #pragma unroll 5
    for (int j = 0; j < 25; j++) {
        float s = sb2[j];
        #pragma unroll
        for (int k = 0; k < 50; k++) s = fmaf(a[k], sw2[k * 25 + j], s);
        s = fmaxf(s, 0.f);
        out0 = fmaf(s, sw3[2 * j],     out0);
        out1 = fmaf(s, sw3[2 * j + 1], out1);
    }
    out[(size_t)r * 2]     = out0;
    out[(size_t)r * 2 + 1] = out1;
}

// ---------------- launcher ---------------------------------------------------
static inline int cdiv(int a, int b) { return (a + b - 1) / b; }

template<int KT, int KP, int CH, int JT, int PRO, int EPI>
static void launch_gemm(int M, const float* A, const float* A2,
                        const float* W, const float* bias, float* C,
                        const int* src = nullptr, const int* dst = nullptr,
                        const float* Ta = nullptr, const float* Tb = nullptr) {
    int smem = (25 * JT) * KP * 4 + 80 * KP * 4;
    cudaFuncSetAttribute(gemm4_k<KT, KP, CH, JT, PRO, EPI>,
                         cudaFuncAttributeMaxDynamicSharedMemorySize, smem);
    gemm4_k<KT, KP, CH, JT, PRO, EPI><<<M / 80, dim3(25, 10), smem>>>(
        A, A2, W, bias, C, src, dst, Ta, Tb);
}

extern "C" void kernel_launch(void* const* d_in, const int* in_sizes, int n_in,
                              void* d_out, int out_size) {
    const float* x        = (const float*)d_in[0];
    const float* edge_attr= (const float*)d_in[1];
    const int*   ei       = (const int*)  d_in[2];
    const float* node_w   = (const float*)d_in[3];
    const float* node_b   = (const float*)d_in[4];
    const float* edge_w   = (const float*)d_in[5];
    const float* edge_b   = (const float*)d_in[6];
    const float* gw1      = (const float*)d_in[7];
    const float* gb1      = (const float*)d_in[8];
    const float* gw2      = (const float*)d_in[9];
    const float* gb2      = (const float*)d_in[10];
    const float* bng      = (const float*)d_in[11];
    const float* bnb      = (const float*)d_in[12];
    const float* ew1      = (const float*)d_in[13];
    const float* eb1      = (const float*)d_in[14];
    const float* ew2      = (const float*)d_in[15];
    const float* eb2      = (const float*)d_in[16];
    const float* mw1      = (const float*)d_in[17];
    const float* mb1      = (const float*)d_in[18];
    const float* mw2      = (const float*)d_in[19];
    const float* mb2      = (const float*)d_in[20];
    const float* mw3      = (const float*)d_in[21];
    const float* mb3      = (const float*)d_in[22];
    float* out = (float*)d_out;

    void* p;
    cudaGetSymbolAddress(&p, g_h);    float* h    = (float*)p;
    cudaGetSymbolAddress(&p, g_e);    float* e    = (float*)p;
    cudaGetSymbolAddress(&p, g_agg);  float* agg  = (float*)p;
    cudaGetSymbolAddress(&p, g_t);    float* t    = (float*)p;
    cudaGetSymbolAddress(&p, g_z);    float* z    = (float*)p;
    cudaGetSymbolAddress(&p, g_Ha);   float* Ha   = (float*)p;
    cudaGetSymbolAddress(&p, g_Hb);   float* Hb   = (float*)p;
    cudaGetSymbolAddress(&p, g_HRa);  float* HRa  = (float*)p;
    cudaGetSymbolAddress(&p, g_HRb);  float* HRb  = (float*)p;
    cudaGetSymbolAddress(&p, g_t1);   float* t1   = (float*)p;
    cudaGetSymbolAddress(&p, g_o1);   float* o1   = (float*)p;
    cudaGetSymbolAddress(&p, g_stats);float* st   = (float*)p;
    cudaGetSymbolAddress(&p, g_zb);   float* zb   = (float*)p;

    const int* src = ei;
    const int* dst = ei + Ee;

    zero_k<<<1, 128>>>(zb, Hh);

    // embeddings: KT=64 -> KP=68 (bank step 4, 17 chunks); KT=16 -> KP=20 (step 20, 5 chunks)
    launch_gemm<FIN, 68, 17, 4, 0, 0>(Nn, x,         nullptr, node_w, node_b, h);
    launch_gemm<EIN, 20,  5, 4, 0, 0>(Ee, edge_attr, nullptr, edge_w, edge_b, e);

    for (int l = 0; l < LL; l++) {
        zero_k<<<cdiv(Nn * Hh, 256), 256>>>(agg, Nn * Hh);
        scatter_k<<<Ee, 128>>>(h, e, src, dst, agg);
        // GINE MLP
        launch_gemm<100, 108, 25, 4, 1, 1>(Nn, h, agg, gw1 + (size_t)l * 10000, gb1 + l * Hh, t);
        launch_gemm<100, 108, 25, 4, 0, 0>(Nn, t, nullptr, gw2 + (size_t)l * 10000, gb2 + l * Hh, z);
        // BN + residual
        zero_k<<<1, 256>>>(st, 2 * Hh);
        bn_stats_k<<<cdiv(Nn, 256), 128>>>(z, st);
        hupd_k<<<cdiv(Nn * Hh, 256), 256>>>(h, z, st, bng + l * Hh, bnb + l * Hh);
        // edge-MLP decomposed to node level
        launch_gemm<100, 108, 25, 4, 0, 0>(Nn, h, nullptr, ew1 + (size_t)l * 30000,         zb, Ha);
        launch_gemm<100, 108, 25, 4, 0, 0>(Nn, h, nullptr, ew1 + (size_t)l * 30000 + 10000, zb, Hb);
        // t1 = relu(e@W_c + Ha[src] + Hb[dst] + b1)
        launch_gemm<100, 108, 25, 4, 0, 3>(Ee, e, nullptr, ew1 + (size_t)l * 30000 + 20000,
                                           eb1 + l * Hh, t1, src, dst, Ha, Hb);
        // e += 0.5*(t1@ew2 + b2)
        launch_gemm<100, 108, 25, 4, 0, 2>(Ee, t1, nullptr, ew2 + (size_t)l * 10000, eb2 + l * Hh, e);
    }

    // readout (node-level decomposition of mlp_w1)
    launch_gemm<100, 108, 25, 2, 2, 0>(Nn, h, nullptr, mw1,        zb, HRa);
    launch_gemm<100, 108, 25, 2, 2, 0>(Nn, h, nullptr, mw1 + 5000, zb, HRb);
    launch_gemm<100, 108, 25, 2, 0, 3>(Ee, e, nullptr, mw1 + 10000, mb1, o1, src, dst, HRa, HRb);
    final_fused_k<<<cdiv(Ee, 256), 256>>>(o1, mw2, mb2, mw3, mb3, out);
}

// round 6
// speedup vs baseline: 2.4368x; 1.0712x over previous
#include <cuda_runtime.h>
#include <math.h>
#include <string.h>

#define Nn   50000
#define Ee   500000
#define FIN  64
#define EIN  16
#define Hh   100
#define LL   2
#define BN_EPS 1e-5f

// ---------------- scratch (static device globals; no allocation) -------------
__device__ float g_h   [Nn * Hh];
__device__ float g_e   [(size_t)Ee * Hh];
__device__ float g_agg [Nn * Hh];
__device__ float g_t   [Nn * Hh];
__device__ float g_z   [Nn * Hh];
__device__ float g_Ha  [Nn * Hh];
__device__ float g_Hb  [Nn * Hh];
__device__ float g_HRa [Nn * 50];
__device__ float g_HRb [Nn * 50];
__device__ float g_t1  [(size_t)Ee * Hh];
__device__ float g_o1  [(size_t)Ee * 50];
__device__ float g_stats[2 * Hh];
__device__ float g_wt  [154600];     // transposed, K-padded weights

// ---------------- weight transpose (once per launch) -------------------------
#define NJOBS 17
struct TransJobs {
    const float* src[NJOBS];
    int K[NJOBS], J[NJOBS], KT[NJOBS], dstOff[NJOBS];
};

__global__ void trans_k(TransJobs tj, float* __restrict__ wt) {
    int job = blockIdx.x;
    const float* s = tj.src[job];
    float* d = wt + tj.dstOff[job];
    int K = tj.K[job], J = tj.J[job], KT = tj.KT[job];
    int n = J * KT;
    for (int idx = threadIdx.x; idx < n; idx += blockDim.x) {
        int j = idx / KT, k = idx - j * KT;
        d[idx] = (k < K) ? s[k * J + j] : 0.f;
    }
}

// zero agg + stats in one launch
__global__ void zero2_k(float* __restrict__ agg, float* __restrict__ st) {
    int i = blockIdx.x * blockDim.x + threadIdx.x;
    if (i < Nn * Hh) agg[i] = 0.f;
    if (i < 2 * Hh) st[i] = 0.f;
}

// ---------------- scatter: warp per edge, float4 -----------------------------
__global__ void __launch_bounds__(256)
scatter_k(const float* __restrict__ h, const float* __restrict__ e,
          const int* __restrict__ src, const int* __restrict__ dst,
          float* __restrict__ agg) {
    int ed = blockIdx.x * 8 + (threadIdx.x >> 5);
    int lane = threadIdx.x & 31;
    if (lane >= 25) return;
    int s = src[ed], d = dst[ed];
    float4 hv = ((const float4*)(h + (size_t)s * Hh))[lane];
    float4 ev = ((const float4*)(e + (size_t)ed * Hh))[lane];
    float* ar = agg + (size_t)d * Hh + 4 * lane;
    float m0 = hv.x + ev.x, m1 = hv.y + ev.y, m2 = hv.z + ev.z, m3 = hv.w + ev.w;
    if (m0 > 0.f) atomicAdd(ar + 0, m0);
    if (m1 > 0.f) atomicAdd(ar + 1, m1);
    if (m2 > 0.f) atomicAdd(ar + 2, m2);
    if (m3 > 0.f) atomicAdd(ar + 3, m3);
}

__global__ void bn_stats_k(const float* __restrict__ z, float* __restrict__ stats) {
    int j = threadIdx.x;
    if (j >= Hh) return;
    int r0 = blockIdx.x * 256;
    int r1 = min(r0 + 256, Nn);
    float s = 0.f, ss = 0.f;
    for (int r = r0; r < r1; r++) {
        float v = z[(size_t)r * Hh + j];
        s += v;
        ss = fmaf(v, v, ss);
    }
    atomicAdd(&stats[j], s);
    atomicAdd(&stats[Hh + j], ss);
}

__global__ void hupd_k(float* __restrict__ h, const float* __restrict__ z,
                       const float* __restrict__ stats,
                       const float* __restrict__ gamma, const float* __restrict__ beta) {
    int idx = blockIdx.x * blockDim.x + threadIdx.x;
    if (idx >= Nn * Hh) return;
    int j = idx % Hh;
    float mu  = stats[j] * (1.0f / Nn);
    float var = fmaf(-mu, mu, stats[Hh + j] * (1.0f / Nn));
    float zn  = (z[idx] - mu) * rsqrtf(var + BN_EPS) * gamma[j] + beta[j];
    h[idx] = (h[idx] + fmaxf(zn, 0.f)) * 0.5f;
}

// ---------------- K-paired packed-fp32 GEMM, pre-transposed W ----------------
// C[M, 25*JT] = op(A)[M,KIN] @ W  with Wt pre-transposed+padded [JN][KT].
// Tile 100 rows x 25*JT cols. Block (25,10). Thread: 10 rows x JT cols.
// K-split float2 accumulators; all inner-loop loads LDS.128; KT/4 odd => conflict-free.
// PRO: 0 plain, 1 A+A2, 2 relu(A)
// EPI: 0 store+bias, 1 relu store, 2 C += 0.5*(acc+bias),
//      3 relu(acc+bias+Ta[src]+Tb[dst]), 4 raw store (no bias)
template<int KIN, int KT, int JT, int PRO, int EPI>
__global__ void __launch_bounds__(256, 2)
gemm5_k(const float* __restrict__ A, const float* __restrict__ A2,
        const float* __restrict__ Wt, const float* __restrict__ bias,
        float* __restrict__ C,
        const int* __restrict__ src, const int* __restrict__ dst,
        const float* __restrict__ Ta, const float* __restrict__ Tb) {
    constexpr int JN = 25 * JT;
    constexpr int C4 = KT / 4;
    extern __shared__ float sm[];
    float* Ws = sm;             // [JN][KT]
    float* As = sm + JN * KT;   // [100][KT]
    const int x = threadIdx.x, y = threadIdx.y;
    const int tid = y * 25 + x;
    const int row0 = blockIdx.x * 100;

    // W: straight vectorized copy (pre-transposed, padded)
    for (int idx = tid; idx < JN * KT / 4; idx += 250)
        ((float4*)Ws)[idx] = ((const float4*)Wt)[idx];
    // A tile (coalesced), with op
    for (int idx = tid; idx < 100 * KIN; idx += 250) {
        int i = idx / KIN, k = idx - i * KIN;
        float v = A[(size_t)(row0 + i) * KIN + k];
        if (PRO == 1) v += A2[(size_t)(row0 + i) * KIN + k];
        if (PRO == 2) v = fmaxf(v, 0.f);
        As[i * KT + k] = v;
    }
    if (KT > KIN) {
        constexpr int PD = KT - KIN;
        for (int idx = tid; idx < 100 * PD; idx += 250) {
            int i = idx / PD, k = KIN + idx - i * PD;
            As[i * KT + k] = 0.f;
        }
    }
    __syncthreads();

    unsigned long long acc[10][JT];
    #pragma unroll
    for (int r = 0; r < 10; r++)
        #pragma unroll
        for (int q = 0; q < JT; q++) acc[r][q] = 0ULL;

    const ulonglong2* WsU = (const ulonglong2*)Ws;
    const ulonglong2* AsU = (const ulonglong2*)As;

    #pragma unroll 3
    for (int c = 0; c < C4; c++) {
        ulonglong2 b[JT];
        #pragma unroll
        for (int q = 0; q < JT; q++) b[q] = WsU[(x + 25 * q) * C4 + c];
        #pragma unroll
        for (int r = 0; r < 10; r++) {
            ulonglong2 a = AsU[(y + 10 * r) * C4 + c];
            #pragma unroll
            for (int q = 0; q < JT; q++) {
                asm("fma.rn.f32x2 %0, %1, %2, %0;" : "+l"(acc[r][q]) : "l"(a.x), "l"(b[q].x));
                asm("fma.rn.f32x2 %0, %1, %2, %0;" : "+l"(acc[r][q]) : "l"(a.y), "l"(b[q].y));
            }
        }
    }

    #pragma unroll
    for (int r = 0; r < 10; r++) {
        int row = row0 + y + 10 * r;
        const float* ta = nullptr; const float* tb = nullptr;
        if (EPI == 3) {
            ta = Ta + (size_t)src[row] * JN;
            tb = Tb + (size_t)dst[row] * JN;
        }
        #pragma unroll
        for (int q = 0; q < JT; q++) {
            int j = x + 25 * q;
            float2 f;
            memcpy(&f, &acc[r][q], 8);
            float v = f.x + f.y;
            if (EPI != 4) v += bias[j];
            float* cp = C + (size_t)row * JN + j;
            if (EPI == 0)      *cp = v;
            else if (EPI == 1) *cp = fmaxf(v, 0.f);
            else if (EPI == 2) *cp = fmaf(0.5f, v, *cp);
            else if (EPI == 3) *cp = fmaxf(v + ta[j] + tb[j], 0.f);
            else               *cp = v;
        }
    }
}

// fused tail: out = relu(o1@w2+b2) @ w3 + b3 per edge
__global__ void __launch_bounds__(256)
final_fused_k(const float* __restrict__ o1,
              const float* __restrict__ w2, const float* __restrict__ b2,
              const float* __restrict__ w3, const float* __restrict__ b3,
              float* __restrict__ out) {
    __shared__ float sw2[50 * 25];
    __shared__ float sw3[50];
    __shared__ float sb2[25];
    __shared__ float sb3[2];
    int t = threadIdx.x;
    for (int i = t; i < 1250; i += 256) sw2[i] = w2[i];
    if (t < 50) sw3[t] = w3[t];
    if (t < 25) sb2[t] = b2[t];
    if (t < 2)  sb3[t] = b3[t];
    __syncthreads();
    int r = blockIdx.x * 256 + t;
    if (r >= Ee) return;
    float a[50];
    const float2* row = (const float2*)(o1 + (size_t)r * 50);
    #pragma unroll
    for (int i = 0; i < 25; i++) { float2 v = row[i]; a[2*i] = v.x; a[2*i+1] = v.y; }
    float out0 = sb3[0], out1 = sb3[1];
    #pragma unroll 5
    for (int j = 0; j < 25; j++) {
        float s = sb2[j];
        #pragma unroll
        for (int k = 0; k < 50; k++) s = fmaf(a[k], sw2[k * 25 + j], s);
        s = fmaxf(s, 0.f);
        out0 = fmaf(s, sw3[2 * j],     out0);
        out1 = fmaf(s, sw3[2 * j + 1], out1);
    }
    out[(size_t)r * 2]     = out0;
    out[(size_t)r * 2 + 1] = out1;
}

// ---------------- launcher ---------------------------------------------------
static inline int cdiv(int a, int b) { return (a + b - 1) / b; }

template<int KIN, int KT, int JT, int PRO, int EPI>
static void launch_gemm(int M, const float* A, const float* A2,
                        const float* Wt, const float* bias, float* C,
                        const int* src = nullptr, const int* dst = nullptr,
                        const float* Ta = nullptr, const float* Tb = nullptr) {
    int smem = (25 * JT) * KT * 4 + 100 * KT * 4;
    cudaFuncSetAttribute(gemm5_k<KIN, KT, JT, PRO, EPI>,
                         cudaFuncAttributeMaxDynamicSharedMemorySize, smem);
    gemm5_k<KIN, KT, JT, PRO, EPI><<<M / 100, dim3(25, 10), smem>>>(
        A, A2, Wt, bias, C, src, dst, Ta, Tb);
}

extern "C" void kernel_launch(void* const* d_in, const int* in_sizes, int n_in,
                              void* d_out, int out_size) {
    const float* x        = (const float*)d_in[0];
    const float* edge_attr= (const float*)d_in[1];
    const int*   ei       = (const int*)  d_in[2];
    const float* node_w   = (const float*)d_in[3];
    const float* node_b   = (const float*)d_in[4];
    const float* edge_w   = (const float*)d_in[5];
    const float* edge_b   = (const float*)d_in[6];
    const float* gw1      = (const float*)d_in[7];
    const float* gb1      = (const float*)d_in[8];
    const float* gw2      = (const float*)d_in[9];
    const float* gb2      = (const float*)d_in[10];
    const float* bng      = (const float*)d_in[11];
    const float* bnb      = (const float*)d_in[12];
    const float* ew1      = (const float*)d_in[13];
    const float* eb1      = (const float*)d_in[14];
    const float* ew2      = (const float*)d_in[15];
    const float* eb2      = (const float*)d_in[16];
    const float* mw1      = (const float*)d_in[17];
    const float* mb1      = (const float*)d_in[18];
    const float* mw2      = (const float*)d_in[19];
    const float* mb2      = (const float*)d_in[20];
    const float* mw3      = (const float*)d_in[21];
    const float* mb3      = (const float*)d_in[22];
    float* out = (float*)d_out;

    void* p;
    cudaGetSymbolAddress(&p, g_h);    float* h    = (float*)p;
    cudaGetSymbolAddress(&p, g_e);    float* e    = (float*)p;
    cudaGetSymbolAddress(&p, g_agg);  float* agg  = (float*)p;
    cudaGetSymbolAddress(&p, g_t);    float* t    = (float*)p;
    cudaGetSymbolAddress(&p, g_z);    float* z    = (float*)p;
    cudaGetSymbolAddress(&p, g_Ha);   float* Ha   = (float*)p;
    cudaGetSymbolAddress(&p, g_Hb);   float* Hb   = (float*)p;
    cudaGetSymbolAddress(&p, g_HRa);  float* HRa  = (float*)p;
    cudaGetSymbolAddress(&p, g_HRb);  float* HRb  = (float*)p;
    cudaGetSymbolAddress(&p, g_t1);   float* t1   = (float*)p;
    cudaGetSymbolAddress(&p, g_o1);   float* o1   = (float*)p;
    cudaGetSymbolAddress(&p, g_stats);float* st   = (float*)p;
    cudaGetSymbolAddress(&p, g_wt);   float* wt   = (float*)p;

    const int* src = ei;
    const int* dst = ei + Ee;

    // ---- transpose weights (1 launch) ----
    // offsets into g_wt
    const int O_NODE = 0, O_EDGE = 6800, O_GW1 = 8800, O_GW2 = 30400,
              O_EW1 = 52000, O_EW2 = 116800, O_MW1 = 138400;
    TransJobs tj;
    int ji = 0;
    auto addjob = [&](const float* s, int K, int J, int KT, int off) {
        tj.src[ji] = s; tj.K[ji] = K; tj.J[ji] = J; tj.KT[ji] = KT; tj.dstOff[ji] = off; ji++;
    };
    addjob(node_w, 64, 100, 68, O_NODE);
    addjob(edge_w, 16, 100, 20, O_EDGE);
    for (int l = 0; l < 2; l++) addjob(gw1 + l * 10000, 100, 100, 108, O_GW1 + l * 10800);
    for (int l = 0; l < 2; l++) addjob(gw2 + l * 10000, 100, 100, 108, O_GW2 + l * 10800);
    for (int l = 0; l < 2; l++)
        for (int q = 0; q < 3; q++)
            addjob(ew1 + l * 30000 + q * 10000, 100, 100, 108, O_EW1 + (l * 3 + q) * 10800);
    for (int l = 0; l < 2; l++) addjob(ew2 + l * 10000, 100, 100, 108, O_EW2 + l * 10800);
    for (int q = 0; q < 3; q++) addjob(mw1 + q * 5000, 100, 50, 108, O_MW1 + q * 5400);
    trans_k<<<NJOBS, 256>>>(tj, wt);

    // embeddings
    launch_gemm<FIN, 68, 4, 0, 0>(Nn, x,         nullptr, wt + O_NODE, node_b, h);
    launch_gemm<EIN, 20, 4, 0, 0>(Ee, edge_attr, nullptr, wt + O_EDGE, edge_b, e);

    for (int l = 0; l < LL; l++) {
        zero2_k<<<cdiv(Nn * Hh, 256), 256>>>(agg, st);
        scatter_k<<<Ee / 8, 256>>>(h, e, src, dst, agg);
        // GINE MLP
        launch_gemm<100, 108, 4, 1, 1>(Nn, h, agg, wt + O_GW1 + l * 10800, gb1 + l * Hh, t);
        launch_gemm<100, 108, 4, 0, 0>(Nn, t, nullptr, wt + O_GW2 + l * 10800, gb2 + l * Hh, z);
        bn_stats_k<<<cdiv(Nn, 256), 128>>>(z, st);
        hupd_k<<<cdiv(Nn * Hh, 256), 256>>>(h, z, st, bng + l * Hh, bnb + l * Hh);
        // edge-MLP decomposed to node level
        launch_gemm<100, 108, 4, 0, 4>(Nn, h, nullptr, wt + O_EW1 + (l * 3 + 0) * 10800, nullptr, Ha);
        launch_gemm<100, 108, 4, 0, 4>(Nn, h, nullptr, wt + O_EW1 + (l * 3 + 1) * 10800, nullptr, Hb);
        launch_gemm<100, 108, 4, 0, 3>(Ee, e, nullptr, wt + O_EW1 + (l * 3 + 2) * 10800,
                                       eb1 + l * Hh, t1, src, dst, Ha, Hb);
        launch_gemm<100, 108, 4, 0, 2>(Ee, t1, nullptr, wt + O_EW2 + l * 10800, eb2 + l * Hh, e);
    }

    // readout (node-level decomposition of mlp_w1)
    launch_gemm<100, 108, 2, 2, 4>(Nn, h, nullptr, wt + O_MW1,        nullptr, HRa);
    launch_gemm<100, 108, 2, 2, 4>(Nn, h, nullptr, wt + O_MW1 + 5400, nullptr, HRb);
    launch_gemm<100, 108, 2, 0, 3>(Ee, e, nullptr, wt + O_MW1 + 10800, mb1, o1, src, dst, HRa, HRb);
    final_fused_k<<<cdiv(Ee, 256), 256>>>(o1, mw2, mb2, mw3, mb3, out);
}